// round 15
// baseline (speedup 1.0000x reference)
#include <cuda_runtime.h>
#include <cuda_fp16.h>
#include <math.h>
#include <stdint.h>

#define BATCH 128
#define SEQT  1024
#define NSTEP 1023
#define IND   256
#define HID   1024
#define OUTD  128
#define NCTA  128

// ---- main-kernel SMEM layout (bytes) ----
// [weights 64KB][A bufs: 4 x 34816 ring]; gm aliases bufs 0-1 (dead post-loop)
#define ABUFB   34816
#define ABASE   65536
#define AROWB   272
#define GMOFF   65536
#define GMSZ    18432
#define SM_MAIN 204800

// ---- gx kernel ----
#define GX_AROWB 528
#define GX_BOFF  67584
#define GX_SM    133120

// ---- head kernel ----
#define HD_AROWB 272
#define HD_BOFF  34816
#define HD_SM    67584

// Scratch (device globals — allocation inside kernel_launch is forbidden).
__device__ __half    g_hall[(size_t)NSTEP * BATCH * HID];       // h_t, f16
__device__ __half    g_gxb[(size_t)NSTEP * BATCH * 4 * HID];    // x-gates + biases
__device__ unsigned  g_bar;                                      // end-of-kernel epoch barrier
__device__ unsigned  g_flag[NCTA * 32];                          // per-CTA step counter, 128B strided

// ---------------------------------------------------------------------------
__device__ __forceinline__ uint32_t smem_u32(const void* p) {
    uint32_t a;
    asm("{ .reg .u64 t; cvta.to.shared.u64 t, %1; cvt.u32.u64 %0, t; }" : "=r"(a) : "l"(p));
    return a;
}

__device__ __forceinline__ void mma_f16(float* d, const uint32_t* a,
                                        uint32_t b0, uint32_t b1)
{
    asm volatile(
        "mma.sync.aligned.m16n8k16.row.col.f32.f16.f16.f32 "
        "{%0,%1,%2,%3}, {%4,%5,%6,%7}, {%8,%9}, {%0,%1,%2,%3};"
        : "+f"(d[0]), "+f"(d[1]), "+f"(d[2]), "+f"(d[3])
        : "r"(a[0]), "r"(a[1]), "r"(a[2]), "r"(a[3]), "r"(b0), "r"(b1));
}

#define LDSM_X4(r, addr) \
    asm volatile("ldmatrix.sync.aligned.m8n8.x4.shared.b16 {%0,%1,%2,%3}, [%4];" \
        : "=r"((r)[0]), "=r"((r)[1]), "=r"((r)[2]), "=r"((r)[3]) : "r"(addr))

__device__ __forceinline__ void cp_async16(uint32_t dst, const void* src) {
    asm volatile("cp.async.cg.shared.global [%0], [%1], 16;" :: "r"(dst), "l"(src));
}
#define CP_COMMIT() asm volatile("cp.async.commit_group;" ::: "memory")
#define CP_WAIT(n)  asm volatile("cp.async.wait_group %0;" :: "n"(n) : "memory")

__device__ __forceinline__ float sigmoid_f(float x)
{
    float e, r;
    asm("ex2.approx.f32 %0, %1;" : "=f"(e) : "f"(-1.4426950408889634f * x));
    asm("rcp.approx.f32 %0, %1;" : "=f"(r) : "f"(1.0f + e));
    return r;
}
__device__ __forceinline__ float tanh_f(float x)
{
    return 2.0f * sigmoid_f(2.0f * x) - 1.0f;
}

// single-writer flag publish (release) / consumer spin (acquire)
__device__ __forceinline__ void flag_publish(unsigned* p, unsigned v)
{
    asm volatile("st.release.gpu.u32 [%0], %1;" :: "l"(p), "r"(v) : "memory");
}
__device__ __forceinline__ void flag_wait(const unsigned* p, unsigned target)
{
    unsigned v;
    do {
        asm volatile("ld.acquire.gpu.u32 %0, [%1];" : "=r"(v) : "l"(p));
    } while (v < target);
}

// Replay-safe epoch barrier (monotonic; validated rounds 2-14). End-of-kernel only.
__device__ __forceinline__ void grid_barrier()
{
    __syncthreads();
    if (threadIdx.x == 0) {
        __threadfence();
        unsigned old    = atomicAdd(&g_bar, 1u);
        unsigned target = (old / NCTA + 1u) * NCTA;
        unsigned cur;
        do {
            asm volatile("ld.acquire.gpu.u32 %0, [%1];" : "=r"(cur) : "l"(&g_bar));
        } while (cur < target);
    }
    __syncthreads();
}

// No-op: shifts ncu's `-s 5` window; harness pre-issues 2 launches (measured
// R13/R14), so harness(0,1), noop(2,3), gx(4), lstm(5) -> ncu captures lstm.
__global__ void noop_kernel() {}

// ---------------------------------------------------------------------------
// gx precompute: gxb[t][b][n] = x_t @ W_ih^T + b_ih + b_hh   (f16 out)
// ---------------------------------------------------------------------------
__global__ __launch_bounds__(512, 1) void gx_kernel(
    const float* __restrict__ seq, const float* __restrict__ Wih,
    const float* __restrict__ bih, const float* __restrict__ bhh)
{
    extern __shared__ __align__(16) char smem[];
    const int tid = threadIdx.x, warp = tid >> 5, lane = tid & 31;
    const int mg = warp & 3, ng = warp >> 2;
    const int tig = lane & 3, grp = lane >> 2;
    const int t = blockIdx.y, n0 = blockIdx.x * 128;

#pragma unroll
    for (int i = 0; i < 16; i++) {
        const int idx4 = i * 512 + tid;
        const int row = idx4 >> 6, q = idx4 & 63;
        float4 v = *(const float4*)(seq + ((size_t)row * SEQT + t) * IND + q * 4);
        char* dst = smem + row * GX_AROWB + q * 8;
        *(__half2*)(dst)     = __floats2half2_rn(v.x, v.y);
        *(__half2*)(dst + 4) = __floats2half2_rn(v.z, v.w);
    }
    {
        __half2* Bh = (__half2*)(smem + GX_BOFF);
        for (int idx = tid; idx < 16 * 16 * 32; idx += 512) {
            const int c = idx >> 9, nt = (idx >> 5) & 15, ln = idx & 31;
            const int n = n0 + nt * 8 + (ln >> 2);
            const float* wp = Wih + (size_t)n * IND + c * 16 + (ln & 3) * 2;
            Bh[(c * 16 + nt) * 64 + ln * 2 + 0] = __floats2half2_rn(wp[0], wp[1]);
            Bh[(c * 16 + nt) * 64 + ln * 2 + 1] = __floats2half2_rn(wp[8], wp[9]);
        }
    }
    __syncthreads();

    float acc[2][4][4];
#pragma unroll
    for (int mt = 0; mt < 2; mt++)
#pragma unroll
        for (int nt = 0; nt < 4; nt++)
#pragma unroll
            for (int j = 0; j < 4; j++) acc[mt][nt][j] = 0.f;

#pragma unroll
    for (int c = 0; c < 16; c++) {
        uint32_t a[2][4];
#pragma unroll
        for (int mt = 0; mt < 2; mt++) {
            const int ra = mg * 32 + mt * 16 + grp;
            const int off = ra * GX_AROWB + c * 32 + tig * 4;
            a[mt][0] = *(const uint32_t*)(smem + off);
            a[mt][2] = *(const uint32_t*)(smem + off + 16);
            a[mt][1] = *(const uint32_t*)(smem + off + 8 * GX_AROWB);
            a[mt][3] = *(const uint32_t*)(smem + off + 8 * GX_AROWB + 16);
        }
#pragma unroll
        for (int nt = 0; nt < 4; nt++) {
            uint2 b = *(const uint2*)(smem + GX_BOFF +
                        ((c * 16 + ng * 4 + nt) * 64 + lane * 2) * 4);
#pragma unroll
            for (int mt = 0; mt < 2; mt++) mma_f16(acc[mt][nt], a[mt], b.x, b.y);
        }
    }

#pragma unroll
    for (int mt = 0; mt < 2; mt++) {
        const int ra = mg * 32 + mt * 16 + grp;
#pragma unroll
        for (int nt = 0; nt < 4; nt++) {
            const int col = ng * 32 + nt * 8 + tig * 2;
            const int ngl = n0 + col;
            const float b0 = bih[ngl] + bhh[ngl];
            const float b1 = bih[ngl + 1] + bhh[ngl + 1];
            __half* o0 = g_gxb + ((size_t)t * BATCH + ra) * (4 * HID) + ngl;
            __half* o1 = g_gxb + ((size_t)t * BATCH + ra + 8) * (4 * HID) + ngl;
            *(__half2*)o0 = __floats2half2_rn(acc[mt][nt][0] + b0, acc[mt][nt][1] + b1);
            *(__half2*)o1 = __floats2half2_rn(acc[mt][nt][2] + b0, acc[mt][nt][3] + b1);
        }
    }
}

// ---------------------------------------------------------------------------
// Persistent fp16 LSTM — flag-pipelined (NO per-step global barrier).
// 128 CTAs x 512 threads; CTA owns 8 units = 32 gate cols; warp (mg, kh):
// M32 x N32 x K256-of-1024. 8 stages of K128 via cp.async 4-buffer ring,
// issued 3 ahead. Cross-CTA sync: flag[c] = completed steps of CTA c
// (single-writer release store). Stage s of step t reads h cols
// [128s,128s+128) = output of CTAs [16s,16s+16) -> gate each cp.async issue
// on those 16 flags (16 parallel pollers + the existing stage sync).
// CTAs drift freely; h_t buffers are per-step (no WAR hazards).
// ---------------------------------------------------------------------------
__global__ __launch_bounds__(512, 1) void lstm_f16_kernel(const float* __restrict__ Whh)
{
    extern __shared__ __align__(16) char smem[];
    const uint32_t sb = smem_u32(smem);
    const int tid = threadIdx.x, warp = tid >> 5, lane = tid & 31;
    const int mg = warp & 3, kh = warp >> 2;
    const int tig = lane & 3, grp = lane >> 2;
    const int cta = blockIdx.x;

    // resident weight fragments, chunk-paired layout (64KB)
    {
        __half2* Bw = (__half2*)smem;
        for (int idx = tid; idx < 64 * 4 * 32; idx += 512) {
            const int c = idx >> 7, g = (idx >> 5) & 3, ln = idx & 31;
            const int p = c >> 1, e = c & 1;
            const float* wp = Whh + (size_t)(g * HID + 8 * cta + (ln >> 2)) * HID
                                  + c * 16 + (ln & 3) * 2;
            __half2* dst = Bw + ((p * 4 + g) * 128 + ln * 4 + e * 2);
            dst[0] = __floats2half2_rn(wp[0], wp[1]);
            dst[1] = __floats2half2_rn(wp[8], wp[9]);
        }
    }

    const uint32_t aoff = (uint32_t)((mg * 32 + (lane & 15)) * AROWB + (lane >> 4) * 16);
    // per-thread staging coordinates (4 x 16B per stage)
    const int srow0 = tid >> 4;
    const int sq    = (tid & 15) * 8;

    const int urow = tid >> 2, um = tid & 3;   // cell-update ownership
    float cst0 = 0.f, cst1 = 0.f;
    __syncthreads();

    for (int t = 0; t < NSTEP; t++) {
        // prefetch gxb early (DRAM latency hidden behind the MMA stages)
        __half2 gx[4];
        {
            const __half* gxp = g_gxb + ((size_t)t * BATCH + urow) * (4 * HID)
                                      + 8 * cta + 2 * um;
#pragma unroll
            for (int g = 0; g < 4; g++) gx[g] = *(const __half2*)(gxp + (size_t)g * HID);
        }

        if (t > 0) {
            const __half* hsrc = g_hall + (size_t)(t - 1) * BATCH * HID;

            // gate stages 0-2 on their 48 producers, then issue (96KB in flight)
            if (tid < 48) flag_wait(&g_flag[tid * 32], (unsigned)t);
            __syncthreads();
#pragma unroll
            for (int s = 0; s < 3; s++) {
                const uint32_t bb = sb + (uint32_t)(ABASE + s * ABUFB);
#pragma unroll
                for (int i = 0; i < 4; i++) {
                    const int row = srow0 + i * 32;
                    cp_async16(bb + (uint32_t)(row * AROWB) + (uint32_t)(sq * 2),
                               hsrc + (size_t)row * HID + s * 128 + sq);
                }
                CP_COMMIT();
            }

            float acc[2][4][4];
#pragma unroll
            for (int mt = 0; mt < 2; mt++)
#pragma unroll
                for (int g = 0; g < 4; g++)
#pragma unroll
                    for (int j = 0; j < 4; j++) acc[mt][g][j] = 0.f;

#pragma unroll
            for (int s = 0; s < 8; s++) {
                // gate the upcoming issue (stage s+3) on its 16 producers
                if (s + 3 < 8 && tid < 16)
                    flag_wait(&g_flag[(16 * (s + 3) + tid) * 32], (unsigned)t);
                if (s < 6)       CP_WAIT(2);
                else if (s == 6) CP_WAIT(1);
                else             CP_WAIT(0);
                __syncthreads();

                if (s + 3 < 8) {
                    const int sn = s + 3;
                    const uint32_t bb = sb + (uint32_t)(ABASE + (sn & 3) * ABUFB);
#pragma unroll
                    for (int i = 0; i < 4; i++) {
                        const int row = srow0 + i * 32;
                        cp_async16(bb + (uint32_t)(row * AROWB) + (uint32_t)(sq * 2),
                                   hsrc + (size_t)row * HID + sn * 128 + sq);
                    }
                    CP_COMMIT();
                }

                const uint32_t ab = sb + (uint32_t)(ABASE + (s & 3) * ABUFB);

                // A fragments: 4 x ldmatrix.x4 (2 chunks x 2 m16 tiles)
                uint32_t a[2][2][4];
#pragma unroll
                for (int c2 = 0; c2 < 2; c2++)
#pragma unroll
                    for (int mt = 0; mt < 2; mt++)
                        LDSM_X4(a[c2][mt],
                                ab + (uint32_t)(mt * 16 * AROWB + (kh * 2 + c2) * 32) + aoff);

                // B: one uint4 per gate covers both chunks (pair pb = s*4+kh)
                const int pb = s * 4 + kh;
#pragma unroll
                for (int g = 0; g < 4; g++) {
                    uint4 b = *(const uint4*)(smem + (size_t)((pb * 4 + g) * 512 + lane * 16));
#pragma unroll
                    for (int mt = 0; mt < 2; mt++) {
                        mma_f16(acc[mt][g], a[0][mt], b.x, b.y);
                        mma_f16(acc[mt][g], a[1][mt], b.z, b.w);
                    }
                }
            }
            __syncthreads();   // stage-7 reads done before gm overwrites bufs 0-1

            // gate-partial exchange: gm[kh][128 x 36f] (aliases bufs 0-1, now dead)
            float* gm = (float*)(smem + GMOFF + kh * GMSZ);
#pragma unroll
            for (int mt = 0; mt < 2; mt++) {
                const int ra = mg * 32 + mt * 16 + grp;
#pragma unroll
                for (int g = 0; g < 4; g++) {
                    const int col = g * 8 + tig * 2;
                    *(float2*)(gm + ra * 36 + col) =
                        make_float2(acc[mt][g][0], acc[mt][g][1]);
                    *(float2*)(gm + (ra + 8) * 36 + col) =
                        make_float2(acc[mt][g][2], acc[mt][g][3]);
                }
            }
            __syncthreads();
        }

        // pass C: thread updates (urow, units 2um, 2um+1)
        float gg[4][2];
#pragma unroll
        for (int g = 0; g < 4; g++) {
            float2 xf = __half22float2(gx[g]);
            float s0 = xf.x, s1 = xf.y;
            if (t > 0) {
                const int col = g * 8 + 2 * um;
#pragma unroll
                for (int k = 0; k < 4; k++) {
                    const float* gm = (const float*)(smem + GMOFF + k * GMSZ);
                    float2 v = *(const float2*)(gm + urow * 36 + col);
                    s0 += v.x; s1 += v.y;
                }
            }
            gg[g][0] = s0; gg[g][1] = s1;
        }
        float h0, h1;
        {
            const float si = sigmoid_f(gg[0][0]);
            const float sf = sigmoid_f(gg[1][0]);
            const float tg = tanh_f(gg[2][0]);
            const float so = sigmoid_f(gg[3][0]);
            cst0 = sf * cst0 + si * tg;
            h0 = so * tanh_f(cst0);
        }
        {
            const float si = sigmoid_f(gg[0][1]);
            const float sf = sigmoid_f(gg[1][1]);
            const float tg = tanh_f(gg[2][1]);
            const float so = sigmoid_f(gg[3][1]);
            cst1 = sf * cst1 + si * tg;
            h1 = so * tanh_f(cst1);
        }
        *(__half2*)(g_hall + ((size_t)t * BATCH + urow) * HID + 8 * cta + 2 * um) =
            __floats2half2_rn(h0, h1);

        // publish: all h stores done (sync; also orders gm reads before the
        // next step's staging stores), then release this CTA's step counter.
        __syncthreads();
        if (tid == 0) flag_publish(&g_flag[cta * 32], (unsigned)(t + 1));
    }

    // all CTAs done -> reset flags for the next graph replay (epoch barrier
    // is monotonic and replay-safe; flag reads are all in the past here).
    grid_barrier();
    if (cta == 0 && tid < NCTA) g_flag[tid * 32] = 0;
}

// ---------------------------------------------------------------------------
// Head GEMM + fused log-softmax: out[b][t][v] = logsoftmax_v(h_t . Wout + bout)
// ---------------------------------------------------------------------------
__global__ __launch_bounds__(512, 1) void head_kernel(
    const float* __restrict__ Wout, const float* __restrict__ bout,
    float* __restrict__ out)
{
    extern __shared__ __align__(16) char smem[];
    const int tid = threadIdx.x, warp = tid >> 5, lane = tid & 31;
    const int mg = warp & 3, ng = warp >> 2;
    const int tig = lane & 3, grp = lane >> 2;
    const int t = blockIdx.x;

    float acc[2][4][4];
#pragma unroll
    for (int mt = 0; mt < 2; mt++)
#pragma unroll
        for (int nt = 0; nt < 4; nt++)
#pragma unroll
            for (int j = 0; j < 4; j++) acc[mt][nt][j] = 0.f;

    for (int s = 0; s < 8; s++) {
#pragma unroll
        for (int i = 0; i < 4; i++) {
            const int idx4 = i * 512 + tid;
            *(uint4*)(smem + (idx4 >> 4) * HD_AROWB + (idx4 & 15) * 16) =
                *(const uint4*)(g_hall + ((size_t)t * BATCH + (idx4 >> 4)) * HID
                                + s * 128 + (idx4 & 15) * 8);
        }
        {
            __half2* Bh = (__half2*)(smem + HD_BOFF);
            for (int idx = tid; idx < 8 * 16 * 32; idx += 512) {
                const int c = idx >> 9, nt = (idx >> 5) & 15, ln = idx & 31;
                const int n = nt * 8 + (ln >> 2);
                const float* wp = Wout + (size_t)n * HID + s * 128 + c * 16 + (ln & 3) * 2;
                Bh[(c * 16 + nt) * 64 + ln * 2 + 0] = __floats2half2_rn(wp[0], wp[1]);
                Bh[(c * 16 + nt) * 64 + ln * 2 + 1] = __floats2half2_rn(wp[8], wp[9]);
            }
        }
        __syncthreads();
#pragma unroll
        for (int c = 0; c < 8; c++) {
            uint32_t a[2][4];
#pragma unroll
            for (int mt = 0; mt < 2; mt++) {
                const int ra = mg * 32 + mt * 16 + grp;
                const int off = ra * HD_AROWB + c * 32 + tig * 4;
                a[mt][0] = *(const uint32_t*)(smem + off);
                a[mt][2] = *(const uint32_t*)(smem + off + 16);
                a[mt][1] = *(const uint32_t*)(smem + off + 8 * HD_AROWB);
                a[mt][3] = *(const uint32_t*)(smem + off + 8 * HD_AROWB + 16);
            }
#pragma unroll
            for (int nt = 0; nt < 4; nt++) {
                uint2 b = *(const uint2*)(smem + HD_BOFF +
                            ((c * 16 + ng * 4 + nt) * 64 + lane * 2) * 4);
#pragma unroll
                for (int mt = 0; mt < 2; mt++) mma_f16(acc[mt][nt], a[mt], b.x, b.y);
            }
        }
        __syncthreads();
    }

    // stage logits (+bias) to smem [128 rows x 132 floats]
    float* lg = (float*)smem;
#pragma unroll
    for (int mt = 0; mt < 2; mt++) {
        const int ra = mg * 32 + mt * 16 + grp;
#pragma unroll
        for (int nt = 0; nt < 4; nt++) {
            const int col = ng * 32 + nt * 8 + tig * 2;
            const float b0 = bout[col], b1 = bout[col + 1];
            *(float2*)(lg + ra * 132 + col) =
                make_float2(acc[mt][nt][0] + b0, acc[mt][nt][1] + b1);
            *(float2*)(lg + (ra + 8) * 132 + col) =
                make_float2(acc[mt][nt][2] + b0, acc[mt][nt][3] + b1);
        }
    }
    __syncthreads();

    // log-softmax: 4 threads per row, 32 cols each, butterfly over the 4-group
    {
        const int row = tid >> 2, seg = tid & 3;
        const float* rp = lg + row * 132 + seg * 32;
        float v[32];
#pragma unroll
        for (int i = 0; i < 8; i++) *(float4*)&v[i * 4] = *(const float4*)(rp + i * 4);
        float mx = v[0];
#pragma unroll
        for (int i = 1; i < 32; i++) mx = fmaxf(mx, v[i]);
        mx = fmaxf(mx, __shfl_xor_sync(0xffffffffu, mx, 1));
        mx = fmaxf(mx, __shfl_xor_sync(0xffffffffu, mx, 2));
        float sum = 0.f;
#pragma unroll
        for (int i = 0; i < 32; i++) {
            float e;
            asm("ex2.approx.f32 %0, %1;" : "=f"(e)
                : "f"(1.4426950408889634f * (v[i] - mx)));
            sum += e;
        }
        sum += __shfl_xor_sync(0xffffffffu, sum, 1);
        sum += __shfl_xor_sync(0xffffffffu, sum, 2);
        float lg2s;
        asm("lg2.approx.f32 %0, %1;" : "=f"(lg2s) : "f"(sum));
        const float lse = mx + 0.6931471805599453f * lg2s;
        float* op = out + ((size_t)row * NSTEP + t) * OUTD + seg * 32;
#pragma unroll
        for (int i = 0; i < 8; i++)
            *(float4*)(op + i * 4) = make_float4(v[i*4+0] - lse, v[i*4+1] - lse,
                                                 v[i*4+2] - lse, v[i*4+3] - lse);
    }
}

// ---------------------------------------------------------------------------
extern "C" void kernel_launch(void* const* d_in, const int* in_sizes, int n_in,
                              void* d_out, int out_size)
{
    const float* seq  = (const float*)d_in[0];
    const float* Wih  = (const float*)d_in[1];
    const float* Whh  = (const float*)d_in[2];
    const float* bih  = (const float*)d_in[3];
    const float* bhh  = (const float*)d_in[4];
    const float* Wout = (const float*)d_in[5];
    const float* bout = (const float*)d_in[6];
    float* out = (float*)d_out;

    cudaFuncSetAttribute(gx_kernel,       cudaFuncAttributeMaxDynamicSharedMemorySize, GX_SM);
    cudaFuncSetAttribute(lstm_f16_kernel, cudaFuncAttributeMaxDynamicSharedMemorySize, SM_MAIN);
    cudaFuncSetAttribute(head_kernel,     cudaFuncAttributeMaxDynamicSharedMemorySize, HD_SM);

    // 2 noops keep ncu's `-s 5 -c 1` window on lstm_f16_kernel (validated R14).
    noop_kernel<<<1, 32>>>();
    noop_kernel<<<1, 32>>>();

    gx_kernel<<<dim3(32, NSTEP), 512, GX_SM>>>(seq, Wih, bih, bhh);
    lstm_f16_kernel<<<NCTA, 512, SM_MAIN>>>(Whh);
    head_kernel<<<NSTEP, 512, HD_SM>>>(Wout, bout, out);
}

// round 16
// speedup vs baseline: 1.2246x; 1.2246x over previous
#include <cuda_runtime.h>
#include <cuda_fp16.h>
#include <math.h>
#include <stdint.h>

#define BATCH 128
#define SEQT  1024
#define NSTEP 1023
#define IND   256
#define HID   1024
#define OUTD  128
#define NCTA  128

// ---- main-kernel SMEM layout (bytes) ----
// [weights 64KB][A bufs: 4 x 34816 ring]; gm aliases bufs 0-1 (dead post-loop)
#define ABUFB   34816
#define ABASE   65536
#define AROWB   272
#define GMOFF   65536
#define GMSZ    18432
#define SM_MAIN 204800

// ---- gx kernel ----
#define GX_AROWB 528
#define GX_BOFF  67584
#define GX_SM    133120

// ---- head kernel ----
#define HD_AROWB 272
#define HD_BOFF  34816
#define HD_SM    67584

// Scratch (device globals — allocation inside kernel_launch is forbidden).
__device__ __half    g_hall[(size_t)NSTEP * BATCH * HID];       // h_t, f16
__device__ __half    g_gxb[(size_t)NSTEP * BATCH * 4 * HID];    // x-gates + biases
__device__ unsigned  g_bar;                                      // epoch barrier

// ---------------------------------------------------------------------------
__device__ __forceinline__ uint32_t smem_u32(const void* p) {
    uint32_t a;
    asm("{ .reg .u64 t; cvta.to.shared.u64 t, %1; cvt.u32.u64 %0, t; }" : "=r"(a) : "l"(p));
    return a;
}

__device__ __forceinline__ void mma_f16(float* d, const uint32_t* a,
                                        uint32_t b0, uint32_t b1)
{
    asm volatile(
        "mma.sync.aligned.m16n8k16.row.col.f32.f16.f16.f32 "
        "{%0,%1,%2,%3}, {%4,%5,%6,%7}, {%8,%9}, {%0,%1,%2,%3};"
        : "+f"(d[0]), "+f"(d[1]), "+f"(d[2]), "+f"(d[3])
        : "r"(a[0]), "r"(a[1]), "r"(a[2]), "r"(a[3]), "r"(b0), "r"(b1));
}

#define LDSM_X4(r, addr) \
    asm volatile("ldmatrix.sync.aligned.m8n8.x4.shared.b16 {%0,%1,%2,%3}, [%4];" \
        : "=r"((r)[0]), "=r"((r)[1]), "=r"((r)[2]), "=r"((r)[3]) : "r"(addr))

__device__ __forceinline__ void cp_async16(uint32_t dst, const void* src) {
    asm volatile("cp.async.cg.shared.global [%0], [%1], 16;" :: "r"(dst), "l"(src));
}
#define CP_COMMIT() asm volatile("cp.async.commit_group;" ::: "memory")
#define CP_WAIT(n)  asm volatile("cp.async.wait_group %0;" :: "n"(n) : "memory")

__device__ __forceinline__ float sigmoid_f(float x)
{
    float e, r;
    asm("ex2.approx.f32 %0, %1;" : "=f"(e) : "f"(-1.4426950408889634f * x));
    asm("rcp.approx.f32 %0, %1;" : "=f"(r) : "f"(1.0f + e));
    return r;
}
__device__ __forceinline__ float tanh_f(float x)
{
    return 2.0f * sigmoid_f(2.0f * x) - 1.0f;
}

// No-op: shifts ncu's `-s 5` window; harness pre-issues 2 launches (measured
// R13/R14), so harness(0,1), noop(2,3), gx(4), lstm(5) -> ncu captures lstm.
__global__ void noop_kernel() {}

// ---------------------------------------------------------------------------
// gx precompute: gxb[t][b][n] = x_t @ W_ih^T + b_ih + b_hh   (f16 out)
// ---------------------------------------------------------------------------
__global__ __launch_bounds__(512, 1) void gx_kernel(
    const float* __restrict__ seq, const float* __restrict__ Wih,
    const float* __restrict__ bih, const float* __restrict__ bhh)
{
    extern __shared__ __align__(16) char smem[];
    const int tid = threadIdx.x, warp = tid >> 5, lane = tid & 31;
    const int mg = warp & 3, ng = warp >> 2;
    const int tig = lane & 3, grp = lane >> 2;
    const int t = blockIdx.y, n0 = blockIdx.x * 128;

#pragma unroll
    for (int i = 0; i < 16; i++) {
        const int idx4 = i * 512 + tid;
        const int row = idx4 >> 6, q = idx4 & 63;
        float4 v = *(const float4*)(seq + ((size_t)row * SEQT + t) * IND + q * 4);
        char* dst = smem + row * GX_AROWB + q * 8;
        *(__half2*)(dst)     = __floats2half2_rn(v.x, v.y);
        *(__half2*)(dst + 4) = __floats2half2_rn(v.z, v.w);
    }
    {
        __half2* Bh = (__half2*)(smem + GX_BOFF);
        for (int idx = tid; idx < 16 * 16 * 32; idx += 512) {
            const int c = idx >> 9, nt = (idx >> 5) & 15, ln = idx & 31;
            const int n = n0 + nt * 8 + (ln >> 2);
            const float* wp = Wih + (size_t)n * IND + c * 16 + (ln & 3) * 2;
            Bh[(c * 16 + nt) * 64 + ln * 2 + 0] = __floats2half2_rn(wp[0], wp[1]);
            Bh[(c * 16 + nt) * 64 + ln * 2 + 1] = __floats2half2_rn(wp[8], wp[9]);
        }
    }
    __syncthreads();

    float acc[2][4][4];
#pragma unroll
    for (int mt = 0; mt < 2; mt++)
#pragma unroll
        for (int nt = 0; nt < 4; nt++)
#pragma unroll
            for (int j = 0; j < 4; j++) acc[mt][nt][j] = 0.f;

#pragma unroll
    for (int c = 0; c < 16; c++) {
        uint32_t a[2][4];
#pragma unroll
        for (int mt = 0; mt < 2; mt++) {
            const int ra = mg * 32 + mt * 16 + grp;
            const int off = ra * GX_AROWB + c * 32 + tig * 4;
            a[mt][0] = *(const uint32_t*)(smem + off);
            a[mt][2] = *(const uint32_t*)(smem + off + 16);
            a[mt][1] = *(const uint32_t*)(smem + off + 8 * GX_AROWB);
            a[mt][3] = *(const uint32_t*)(smem + off + 8 * GX_AROWB + 16);
        }
#pragma unroll
        for (int nt = 0; nt < 4; nt++) {
            uint2 b = *(const uint2*)(smem + GX_BOFF +
                        ((c * 16 + ng * 4 + nt) * 64 + lane * 2) * 4);
#pragma unroll
            for (int mt = 0; mt < 2; mt++) mma_f16(acc[mt][nt], a[mt], b.x, b.y);
        }
    }

#pragma unroll
    for (int mt = 0; mt < 2; mt++) {
        const int ra = mg * 32 + mt * 16 + grp;
#pragma unroll
        for (int nt = 0; nt < 4; nt++) {
            const int col = ng * 32 + nt * 8 + tig * 2;
            const int ngl = n0 + col;
            const float b0 = bih[ngl] + bhh[ngl];
            const float b1 = bih[ngl + 1] + bhh[ngl + 1];
            __half* o0 = g_gxb + ((size_t)t * BATCH + ra) * (4 * HID) + ngl;
            __half* o1 = g_gxb + ((size_t)t * BATCH + ra + 8) * (4 * HID) + ngl;
            *(__half2*)o0 = __floats2half2_rn(acc[mt][nt][0] + b0, acc[mt][nt][1] + b1);
            *(__half2*)o1 = __floats2half2_rn(acc[mt][nt][2] + b0, acc[mt][nt][3] + b1);
        }
    }
}

// ---------------------------------------------------------------------------
// Persistent fp16 LSTM (R14 core; barrier split into arrive/wait with the
// next step's gxb prefetch filling the window).
// 128 CTAs x 512 threads; CTA owns 8 units = 32 gate cols. Warp (mg, kh):
// M32 x N32 x K256-of-1024. 8 stages of K128 staged via cp.async.cg into a
// 4-buffer ring, issued 3 stages ahead. ldmatrix A loads, chunk-paired
// resident B, one global epoch barrier per step (arrive -> gx prefetch ->
// wait) — the DRAM gx load overlaps barrier propagation instead of sitting
// on the post-release critical path.
// ---------------------------------------------------------------------------
__global__ __launch_bounds__(512, 1) void lstm_f16_kernel(const float* __restrict__ Whh)
{
    extern __shared__ __align__(16) char smem[];
    const uint32_t sb = smem_u32(smem);
    const int tid = threadIdx.x, warp = tid >> 5, lane = tid & 31;
    const int mg = warp & 3, kh = warp >> 2;
    const int tig = lane & 3, grp = lane >> 2;
    const int cta = blockIdx.x;

    // resident weight fragments, chunk-paired layout (64KB)
    {
        __half2* Bw = (__half2*)smem;
        for (int idx = tid; idx < 64 * 4 * 32; idx += 512) {
            const int c = idx >> 7, g = (idx >> 5) & 3, ln = idx & 31;
            const int p = c >> 1, e = c & 1;
            const float* wp = Whh + (size_t)(g * HID + 8 * cta + (ln >> 2)) * HID
                                  + c * 16 + (ln & 3) * 2;
            __half2* dst = Bw + ((p * 4 + g) * 128 + ln * 4 + e * 2);
            dst[0] = __floats2half2_rn(wp[0], wp[1]);
            dst[1] = __floats2half2_rn(wp[8], wp[9]);
        }
    }

    const uint32_t aoff = (uint32_t)((mg * 32 + (lane & 15)) * AROWB + (lane >> 4) * 16);
    // per-thread staging coordinates (4 x 16B per stage)
    const int srow0 = tid >> 4;
    const int sq    = (tid & 15) * 8;

    const int urow = tid >> 2, um = tid & 3;   // cell-update ownership
    const __half* gx_base = g_gxb + (size_t)urow * (4 * HID) + 8 * cta + 2 * um;
    float cst0 = 0.f, cst1 = 0.f;

    // prefetch gx for t=0
    __half2 gx[4];
#pragma unroll
    for (int g = 0; g < 4; g++)
        gx[g] = *(const __half2*)(gx_base + (size_t)g * HID);

    __syncthreads();

    for (int t = 0; t < NSTEP; t++) {
        if (t > 0) {
            const __half* hsrc = g_hall + (size_t)(t - 1) * BATCH * HID;

            // issue stages 0..2 immediately (3 groups, 96KB in flight)
#pragma unroll
            for (int s = 0; s < 3; s++) {
                const uint32_t bb = sb + (uint32_t)(ABASE + s * ABUFB);
#pragma unroll
                for (int i = 0; i < 4; i++) {
                    const int row = srow0 + i * 32;
                    cp_async16(bb + (uint32_t)(row * AROWB) + (uint32_t)(sq * 2),
                               hsrc + (size_t)row * HID + s * 128 + sq);
                }
                CP_COMMIT();
            }

            float acc[2][4][4];
#pragma unroll
            for (int mt = 0; mt < 2; mt++)
#pragma unroll
                for (int g = 0; g < 4; g++)
#pragma unroll
                    for (int j = 0; j < 4; j++) acc[mt][g][j] = 0.f;

#pragma unroll
            for (int s = 0; s < 8; s++) {
                if (s < 6)       CP_WAIT(2);
                else if (s == 6) CP_WAIT(1);
                else             CP_WAIT(0);
                __syncthreads();

                if (s + 3 < 8) {
                    const int sn = s + 3;
                    const uint32_t bb = sb + (uint32_t)(ABASE + (sn & 3) * ABUFB);
#pragma unroll
                    for (int i = 0; i < 4; i++) {
                        const int row = srow0 + i * 32;
                        cp_async16(bb + (uint32_t)(row * AROWB) + (uint32_t)(sq * 2),
                                   hsrc + (size_t)row * HID + sn * 128 + sq);
                    }
                    CP_COMMIT();
                }

                const uint32_t ab = sb + (uint32_t)(ABASE + (s & 3) * ABUFB);

                // A fragments: 4 x ldmatrix.x4 (2 chunks x 2 m16 tiles)
                uint32_t a[2][2][4];
#pragma unroll
                for (int c2 = 0; c2 < 2; c2++)
#pragma unroll
                    for (int mt = 0; mt < 2; mt++)
                        LDSM_X4(a[c2][mt],
                                ab + (uint32_t)(mt * 16 * AROWB + (kh * 2 + c2) * 32) + aoff);

                // B: one uint4 per gate covers both chunks (pair pb = s*4+kh)
                const int pb = s * 4 + kh;
#pragma unroll
                for (int g = 0; g < 4; g++) {
                    uint4 b = *(const uint4*)(smem + (size_t)((pb * 4 + g) * 512 + lane * 16));
#pragma unroll
                    for (int mt = 0; mt < 2; mt++) {
                        mma_f16(acc[mt][g], a[0][mt], b.x, b.y);
                        mma_f16(acc[mt][g], a[1][mt], b.z, b.w);
                    }
                }
            }
            __syncthreads();   // stage-7 reads done before gm overwrites bufs 0-1

            // gate-partial exchange: gm[kh][128 x 36f] (aliases bufs 0-1, now dead)
            float* gm = (float*)(smem + GMOFF + kh * GMSZ);
#pragma unroll
            for (int mt = 0; mt < 2; mt++) {
                const int ra = mg * 32 + mt * 16 + grp;
#pragma unroll
                for (int g = 0; g < 4; g++) {
                    const int col = g * 8 + tig * 2;
                    *(float2*)(gm + ra * 36 + col) =
                        make_float2(acc[mt][g][0], acc[mt][g][1]);
                    *(float2*)(gm + (ra + 8) * 36 + col) =
                        make_float2(acc[mt][g][2], acc[mt][g][3]);
                }
            }
            __syncthreads();
        }

        // pass C: thread updates (urow, units 2um, 2um+1)
        float gg[4][2];
#pragma unroll
        for (int g = 0; g < 4; g++) {
            float2 xf = __half22float2(gx[g]);
            float s0 = xf.x, s1 = xf.y;
            if (t > 0) {
                const int col = g * 8 + 2 * um;
#pragma unroll
                for (int k = 0; k < 4; k++) {
                    const float* gm = (const float*)(smem + GMOFF + k * GMSZ);
                    float2 v = *(const float2*)(gm + urow * 36 + col);
                    s0 += v.x; s1 += v.y;
                }
            }
            gg[g][0] = s0; gg[g][1] = s1;
        }
        float h0, h1;
        {
            const float si = sigmoid_f(gg[0][0]);
            const float sf = sigmoid_f(gg[1][0]);
            const float tg = tanh_f(gg[2][0]);
            const float so = sigmoid_f(gg[3][0]);
            cst0 = sf * cst0 + si * tg;
            h0 = so * tanh_f(cst0);
        }
        {
            const float si = sigmoid_f(gg[0][1]);
            const float sf = sigmoid_f(gg[1][1]);
            const float tg = tanh_f(gg[2][1]);
            const float so = sigmoid_f(gg[3][1]);
            cst1 = sf * cst1 + si * tg;
            h1 = so * tanh_f(cst1);
        }
        *(__half2*)(g_hall + ((size_t)t * BATCH + urow) * HID + 8 * cta + 2 * um) =
            __floats2half2_rn(h0, h1);

        // ---- split epoch barrier: arrive, overlap gx prefetch, wait ----
        __syncthreads();                       // h stores done
        unsigned bar_old = 0u;
        if (tid == 0) {
            __threadfence();
            bar_old = atomicAdd(&g_bar, 1u);   // arrive (release)
        }
        if (t + 1 < NSTEP) {                   // next-step gx load fills the window
            const __half* gxp = gx_base + (size_t)(t + 1) * BATCH * (4 * HID);
#pragma unroll
            for (int g = 0; g < 4; g++)
                gx[g] = *(const __half2*)(gxp + (size_t)g * HID);
        }
        if (tid == 0) {
            unsigned target = (bar_old / NCTA + 1u) * NCTA;
            unsigned cur;
            do {
                asm volatile("ld.acquire.gpu.u32 %0, [%1];" : "=r"(cur) : "l"(&g_bar));
            } while (cur < target);
        }
        __syncthreads();                       // release broadcast
    }
}

// ---------------------------------------------------------------------------
// Head GEMM + fused log-softmax: out[b][t][v] = logsoftmax_v(h_t . Wout + bout)
// ---------------------------------------------------------------------------
__global__ __launch_bounds__(512, 1) void head_kernel(
    const float* __restrict__ Wout, const float* __restrict__ bout,
    float* __restrict__ out)
{
    extern __shared__ __align__(16) char smem[];
    const int tid = threadIdx.x, warp = tid >> 5, lane = tid & 31;
    const int mg = warp & 3, ng = warp >> 2;
    const int tig = lane & 3, grp = lane >> 2;
    const int t = blockIdx.x;

    float acc[2][4][4];
#pragma unroll
    for (int mt = 0; mt < 2; mt++)
#pragma unroll
        for (int nt = 0; nt < 4; nt++)
#pragma unroll
            for (int j = 0; j < 4; j++) acc[mt][nt][j] = 0.f;

    for (int s = 0; s < 8; s++) {
#pragma unroll
        for (int i = 0; i < 4; i++) {
            const int idx4 = i * 512 + tid;
            *(uint4*)(smem + (idx4 >> 4) * HD_AROWB + (idx4 & 15) * 16) =
                *(const uint4*)(g_hall + ((size_t)t * BATCH + (idx4 >> 4)) * HID
                                + s * 128 + (idx4 & 15) * 8);
        }
        {
            __half2* Bh = (__half2*)(smem + HD_BOFF);
            for (int idx = tid; idx < 8 * 16 * 32; idx += 512) {
                const int c = idx >> 9, nt = (idx >> 5) & 15, ln = idx & 31;
                const int n = nt * 8 + (ln >> 2);
                const float* wp = Wout + (size_t)n * HID + s * 128 + c * 16 + (ln & 3) * 2;
                Bh[(c * 16 + nt) * 64 + ln * 2 + 0] = __floats2half2_rn(wp[0], wp[1]);
                Bh[(c * 16 + nt) * 64 + ln * 2 + 1] = __floats2half2_rn(wp[8], wp[9]);
            }
        }
        __syncthreads();
#pragma unroll
        for (int c = 0; c < 8; c++) {
            uint32_t a[2][4];
#pragma unroll
            for (int mt = 0; mt < 2; mt++) {
                const int ra = mg * 32 + mt * 16 + grp;
                const int off = ra * HD_AROWB + c * 32 + tig * 4;
                a[mt][0] = *(const uint32_t*)(smem + off);
                a[mt][2] = *(const uint32_t*)(smem + off + 16);
                a[mt][1] = *(const uint32_t*)(smem + off + 8 * HD_AROWB);
                a[mt][3] = *(const uint32_t*)(smem + off + 8 * HD_AROWB + 16);
            }
#pragma unroll
            for (int nt = 0; nt < 4; nt++) {
                uint2 b = *(const uint2*)(smem + HD_BOFF +
                            ((c * 16 + ng * 4 + nt) * 64 + lane * 2) * 4);
#pragma unroll
                for (int mt = 0; mt < 2; mt++) mma_f16(acc[mt][nt], a[mt], b.x, b.y);
            }
        }
        __syncthreads();
    }

    // stage logits (+bias) to smem [128 rows x 132 floats]
    float* lg = (float*)smem;
#pragma unroll
    for (int mt = 0; mt < 2; mt++) {
        const int ra = mg * 32 + mt * 16 + grp;
#pragma unroll
        for (int nt = 0; nt < 4; nt++) {
            const int col = ng * 32 + nt * 8 + tig * 2;
            const float b0 = bout[col], b1 = bout[col + 1];
            *(float2*)(lg + ra * 132 + col) =
                make_float2(acc[mt][nt][0] + b0, acc[mt][nt][1] + b1);
            *(float2*)(lg + (ra + 8) * 132 + col) =
                make_float2(acc[mt][nt][2] + b0, acc[mt][nt][3] + b1);
        }
    }
    __syncthreads();

    // log-softmax: 4 threads per row, 32 cols each, butterfly over the 4-group
    {
        const int row = tid >> 2, seg = tid & 3;
        const float* rp = lg + row * 132 + seg * 32;
        float v[32];
#pragma unroll
        for (int i = 0; i < 8; i++) *(float4*)&v[i * 4] = *(const float4*)(rp + i * 4);
        float mx = v[0];
#pragma unroll
        for (int i = 1; i < 32; i++) mx = fmaxf(mx, v[i]);
        mx = fmaxf(mx, __shfl_xor_sync(0xffffffffu, mx, 1));
        mx = fmaxf(mx, __shfl_xor_sync(0xffffffffu, mx, 2));
        float sum = 0.f;
#pragma unroll
        for (int i = 0; i < 32; i++) {
            float e;
            asm("ex2.approx.f32 %0, %1;" : "=f"(e)
                : "f"(1.4426950408889634f * (v[i] - mx)));
            sum += e;
        }
        sum += __shfl_xor_sync(0xffffffffu, sum, 1);
        sum += __shfl_xor_sync(0xffffffffu, sum, 2);
        float lg2s;
        asm("lg2.approx.f32 %0, %1;" : "=f"(lg2s) : "f"(sum));
        const float lse = mx + 0.6931471805599453f * lg2s;
        float* op = out + ((size_t)row * NSTEP + t) * OUTD + seg * 32;
#pragma unroll
        for (int i = 0; i < 8; i++)
            *(float4*)(op + i * 4) = make_float4(v[i*4+0] - lse, v[i*4+1] - lse,
                                                 v[i*4+2] - lse, v[i*4+3] - lse);
    }
}

// ---------------------------------------------------------------------------
extern "C" void kernel_launch(void* const* d_in, const int* in_sizes, int n_in,
                              void* d_out, int out_size)
{
    const float* seq  = (const float*)d_in[0];
    const float* Wih  = (const float*)d_in[1];
    const float* Whh  = (const float*)d_in[2];
    const float* bih  = (const float*)d_in[3];
    const float* bhh  = (const float*)d_in[4];
    const float* Wout = (const float*)d_in[5];
    const float* bout = (const float*)d_in[6];
    float* out = (float*)d_out;

    cudaFuncSetAttribute(gx_kernel,       cudaFuncAttributeMaxDynamicSharedMemorySize, GX_SM);
    cudaFuncSetAttribute(lstm_f16_kernel, cudaFuncAttributeMaxDynamicSharedMemorySize, SM_MAIN);
    cudaFuncSetAttribute(head_kernel,     cudaFuncAttributeMaxDynamicSharedMemorySize, HD_SM);

    // 2 noops keep ncu's `-s 5 -c 1` window on lstm_f16_kernel (validated R14).
    noop_kernel<<<1, 32>>>();
    noop_kernel<<<1, 32>>>();

    gx_kernel<<<dim3(32, NSTEP), 512, GX_SM>>>(seq, Wih, bih, bhh);
    lstm_f16_kernel<<<NCTA, 512, SM_MAIN>>>(Whh);
    head_kernel<<<NSTEP, 512, HD_SM>>>(Wout, bout, out);
}